// round 11
// baseline (speedup 1.0000x reference)
#include <cuda_runtime.h>
#include <cuda_bf16.h>
#include <cuda_fp16.h>
#include <cstdint>

#define D_MODEL 1024
#define NHEADS  16
#define HDIM    64
#define BATCH   2
#define SEQ     2048
#define NROWS   (BATCH * SEQ)   // 4096
#define QTILE   128

// ---------------- scratch (static device globals; no allocations) ----------------
__device__ __half g_Qh[BATCH * NHEADS * SEQ * HDIM];   // [B,H,S,Dh] fp16
__device__ __half g_Kh[BATCH * NHEADS * SEQ * HDIM];
__device__ __half g_Vh[BATCH * NHEADS * SEQ * HDIM];
__device__ __nv_bfloat16 g_Ah[NROWS * D_MODEL];        // A hi: x-split, then ctx-split
__device__ __nv_bfloat16 g_Al[NROWS * D_MODEL];        // A lo
__device__ __nv_bfloat16 g_Wh[4 * D_MODEL * D_MODEL];  // W hi [z][k][n]
__device__ __nv_bfloat16 g_Wl[4 * D_MODEL * D_MODEL];  // W lo

// ---------------- ptx helpers (sm_80-class only; NO tcgen05 on this target) ------
__device__ __forceinline__ void cp16(uint32_t smem, const void* gmem) {
    asm volatile("cp.async.cg.shared.global [%0], [%1], 16;" :: "r"(smem), "l"(gmem));
}
#define CP_COMMIT() asm volatile("cp.async.commit_group;" ::: "memory")
template <int N>
__device__ __forceinline__ void cp_wait() {
    asm volatile("cp.async.wait_group %0;" :: "n"(N) : "memory");
}

__device__ __forceinline__ void ldmatrix_x4(uint32_t& r0, uint32_t& r1,
                                            uint32_t& r2, uint32_t& r3, uint32_t addr) {
    asm volatile("ldmatrix.sync.aligned.m8n8.x4.shared.b16 {%0,%1,%2,%3}, [%4];"
                 : "=r"(r0), "=r"(r1), "=r"(r2), "=r"(r3) : "r"(addr));
}
__device__ __forceinline__ void ldmatrix_x4_trans(uint32_t& r0, uint32_t& r1,
                                                  uint32_t& r2, uint32_t& r3, uint32_t addr) {
    asm volatile("ldmatrix.sync.aligned.m8n8.x4.trans.shared.b16 {%0,%1,%2,%3}, [%4];"
                 : "=r"(r0), "=r"(r1), "=r"(r2), "=r"(r3) : "r"(addr));
}
__device__ __forceinline__ void mma_bf16(float* c,
    uint32_t a0, uint32_t a1, uint32_t a2, uint32_t a3, uint32_t b0, uint32_t b1)
{
    asm volatile(
        "mma.sync.aligned.m16n8k16.row.col.f32.bf16.bf16.f32 "
        "{%0,%1,%2,%3}, {%4,%5,%6,%7}, {%8,%9}, {%0,%1,%2,%3};\n"
        : "+f"(c[0]), "+f"(c[1]), "+f"(c[2]), "+f"(c[3])
        : "r"(a0), "r"(a1), "r"(a2), "r"(a3), "r"(b0), "r"(b1));
}
__device__ __forceinline__ void mma_f16(float* c,
    uint32_t a0, uint32_t a1, uint32_t a2, uint32_t a3, uint32_t b0, uint32_t b1)
{
    asm volatile(
        "mma.sync.aligned.m16n8k16.row.col.f32.f16.f16.f32 "
        "{%0,%1,%2,%3}, {%4,%5,%6,%7}, {%8,%9}, {%0,%1,%2,%3};\n"
        : "+f"(c[0]), "+f"(c[1]), "+f"(c[2]), "+f"(c[3])
        : "r"(a0), "r"(a1), "r"(a2), "r"(a3), "r"(b0), "r"(b1));
}
__device__ __forceinline__ uint32_t pack_f16(float x0, float x1) {
    __half2 h = __floats2half2_rn(x0, x1);
    return *(uint32_t*)&h;
}

// =================================================================================
// Pre-pass: element-wise hi/lo bf16 splits (no transpose; layouts preserved).
// =================================================================================
__global__ __launch_bounds__(256) void split_x_kernel(const float* __restrict__ src)
{
    const size_t i = ((size_t)blockIdx.x * 256 + threadIdx.x) * 4;
    float4 v = *(const float4*)(src + i);
    __nv_bfloat16 h[4] = {__float2bfloat16(v.x), __float2bfloat16(v.y),
                          __float2bfloat16(v.z), __float2bfloat16(v.w)};
    __nv_bfloat16 l[4] = {__float2bfloat16(v.x - __bfloat162float(h[0])),
                          __float2bfloat16(v.y - __bfloat162float(h[1])),
                          __float2bfloat16(v.z - __bfloat162float(h[2])),
                          __float2bfloat16(v.w - __bfloat162float(h[3]))};
    *(uint2*)(g_Ah + i) = *(uint2*)h;
    *(uint2*)(g_Al + i) = *(uint2*)l;
}
__global__ __launch_bounds__(256) void split_w_kernel(
    const float* __restrict__ W0, const float* __restrict__ W1,
    const float* __restrict__ W2, const float* __restrict__ W3)
{
    const float* W = (blockIdx.z == 0) ? W0 : (blockIdx.z == 1) ? W1
                   : (blockIdx.z == 2) ? W2 : W3;
    const size_t o = (size_t)blockIdx.z * D_MODEL * D_MODEL;
    const size_t i = ((size_t)blockIdx.x * 256 + threadIdx.x) * 4;
    float4 v = *(const float4*)(W + i);
    __nv_bfloat16 h[4] = {__float2bfloat16(v.x), __float2bfloat16(v.y),
                          __float2bfloat16(v.z), __float2bfloat16(v.w)};
    __nv_bfloat16 l[4] = {__float2bfloat16(v.x - __bfloat162float(h[0])),
                          __float2bfloat16(v.y - __bfloat162float(h[1])),
                          __float2bfloat16(v.z - __bfloat162float(h[2])),
                          __float2bfloat16(v.w - __bfloat162float(h[3]))};
    *(uint2*)(g_Wh + o + i) = *(uint2*)h;
    *(uint2*)(g_Wl + o + i) = *(uint2*)l;
}

// =================================================================================
// bf16-split 3-pass GEMM v2 (verified Round-10): cp.async double-buffered, BK=32.
// =================================================================================
#define STG_AH 0
#define STG_AL 10240
#define STG_BH 20480
#define STG_BL 29184
#define STG_SZ 37888
#define G2SMEM (2 * STG_SZ)   // 75776

template <int QKV>
__global__ __launch_bounds__(256) void bf16_gemm2(float* __restrict__ Cout)
{
    extern __shared__ uint8_t smem[];
    const uint32_t sb = (uint32_t)__cvta_generic_to_shared(smem);
    const int t = threadIdx.x, lane = t & 31, wid = t >> 5;
    const int g = lane >> 2, tq = lane & 3, quad = lane >> 3, idx8 = lane & 7;
    const int wm = (wid & 1) * 64, wn = (wid >> 1) * 32;
    const int m0 = blockIdx.y * 128, n0 = blockIdx.x * 128;
    const int z  = QKV ? (int)blockIdx.z : 3;

    const __nv_bfloat16* Wh = g_Wh + (size_t)z * D_MODEL * D_MODEL;
    const __nv_bfloat16* Wl = g_Wl + (size_t)z * D_MODEL * D_MODEL;

    const int arow0 = t >> 2;
    const int ak8   = (t & 3) * 8;
    const int brow0 = t >> 4;
    const int bn8   = (t & 15) * 8;

    float acc[4][4][4];
#pragma unroll
    for (int mf = 0; mf < 4; mf++)
#pragma unroll
        for (int nf = 0; nf < 4; nf++)
#pragma unroll
            for (int r = 0; r < 4; r++) acc[mf][nf][r] = 0.0f;

    auto load_stage = [&](int buf, int ks) {
        const uint32_t base = sb + buf * STG_SZ;
#pragma unroll
        for (int half = 0; half < 2; half++) {
            const int row = arow0 + half * 64;
            const uint32_t d = base + row * 80 + (t & 3) * 16;
            const size_t   s = (size_t)(m0 + row) * D_MODEL + ks + ak8;
            cp16(d + STG_AH, g_Ah + s);
            cp16(d + STG_AL, g_Al + s);
        }
#pragma unroll
        for (int half = 0; half < 2; half++) {
            const int row = brow0 + half * 16;
            const uint32_t d = base + row * 272 + (t & 15) * 16;
            const size_t   s = (size_t)(ks + row) * D_MODEL + n0 + bn8;
            cp16(d + STG_BH, Wh + s);
            cp16(d + STG_BL, Wl + s);
        }
        CP_COMMIT();
    };

    load_stage(0, 0);
    load_stage(1, 32);
    int ks = 64;

    constexpr int NIT = D_MODEL / 32;   // 32
    for (int it = 0; it < NIT; ++it) {
        if (it + 1 < NIT) cp_wait<1>(); else cp_wait<0>();
        __syncthreads();

        const uint32_t ab  = sb + (it & 1) * STG_SZ;
        const uint32_t aAh = ab + STG_AH, aAl = ab + STG_AL;
        const uint32_t aBh = ab + STG_BH, aBl = ab + STG_BL;

#pragma unroll
        for (int kb = 0; kb < 2; kb++) {
            uint32_t ah[4][4], al[4][4], bh[4][2], bl[4][2];
#pragma unroll
            for (int mf = 0; mf < 4; mf++) {
                const uint32_t off =
                    (uint32_t)((wm + mf * 16 + (lane & 15)) * 80 +
                               (kb * 8 + (lane >> 4) * 4) * 4);
                ldmatrix_x4(ah[mf][0], ah[mf][1], ah[mf][2], ah[mf][3], aAh + off);
                ldmatrix_x4(al[mf][0], al[mf][1], al[mf][2], al[mf][3], aAl + off);
            }
#pragma unroll
            for (int np = 0; np < 2; np++) {
                const uint32_t boff =
                    (uint32_t)((kb * 16 + (quad & 1) * 8 + idx8) * 272 +
                               (wn / 2 + np * 8 + (quad >> 1) * 4) * 4);
                uint32_t r0, r1, r2, r3;
                ldmatrix_x4_trans(r0, r1, r2, r3, aBh + boff);
                bh[2 * np][0] = r0; bh[2 * np][1] = r1;
                bh[2 * np + 1][0] = r2; bh[2 * np + 1][1] = r3;
                ldmatrix_x4_trans(r0, r1, r2, r3, aBl + boff);
                bl[2 * np][0] = r0; bl[2 * np][1] = r1;
                bl[2 * np + 1][0] = r2; bl[2 * np + 1][1] = r3;
            }
#pragma unroll
            for (int mf = 0; mf < 4; mf++)
#pragma unroll
                for (int nf = 0; nf < 4; nf++)
                    mma_bf16(acc[mf][nf], ah[mf][0], ah[mf][1], ah[mf][2], ah[mf][3],
                             bh[nf][0], bh[nf][1]);
#pragma unroll
            for (int mf = 0; mf < 4; mf++)
#pragma unroll
                for (int nf = 0; nf < 4; nf++)
                    mma_bf16(acc[mf][nf], al[mf][0], al[mf][1], al[mf][2], al[mf][3],
                             bh[nf][0], bh[nf][1]);
#pragma unroll
            for (int mf = 0; mf < 4; mf++)
#pragma unroll
                for (int nf = 0; nf < 4; nf++)
                    mma_bf16(acc[mf][nf], ah[mf][0], ah[mf][1], ah[mf][2], ah[mf][3],
                             bl[nf][0], bl[nf][1]);
        }
        __syncthreads();
        if (it + 2 < NIT) {
            load_stage(it & 1, ks);
            ks += 32;
        }
    }

#pragma unroll
    for (int mf = 0; mf < 4; mf++) {
#pragma unroll
        for (int nf = 0; nf < 4; nf++) {
            const int n = n0 + wn + nf * 8 + 2 * tq;
#pragma unroll
            for (int half = 0; half < 2; half++) {
                const int m = m0 + wm + mf * 16 + g + half * 8;
                const float c0 = acc[mf][nf][half * 2 + 0];
                const float c1 = acc[mf][nf][half * 2 + 1];
                if (QKV) {
                    const int b  = m >> 11;
                    const int s  = m & (SEQ - 1);
                    const int h  = n >> 6;
                    const int dd = n & (HDIM - 1);
                    __half2 hv = __floats2half2_rn(c0, c1);
                    __half* dst = (z == 0) ? g_Qh : (z == 1) ? g_Kh : g_Vh;
                    *(__half2*)&dst[(((size_t)(b * NHEADS + h)) * SEQ + s) * HDIM + dd] = hv;
                } else {
                    *(float2*)&Cout[(size_t)m * D_MODEL + n] = make_float2(c0, c1);
                }
            }
        }
    }
}

// =================================================================================
// fp16 tensor-core causal flash attention with cp.async double-buffered KV tiles.
// Block = 128 queries of one (b,h); 8 warps, warp-local softmax (verified core).
// KV ring: 2 buffers x (64 x 36 words) for each of K and V (36,864 B static smem).
// =================================================================================
#define KVW (64 * 36)        // words per KV buffer (pitch 36)
#define KVB (KVW * 4)        // 9216 bytes

__global__ __launch_bounds__(256) void attn_mma_kernel()
{
    constexpr int KP = 36;
    __shared__ __align__(16) uint32_t Ks[2 * KVW];
    __shared__ __align__(16) uint32_t Vs[2 * KVW];

    const int t    = threadIdx.x;
    const int lane = t & 31;
    const int wid  = t >> 5;
    const int g    = lane >> 2;
    const int tq   = lane & 3;
    const int quad = lane >> 3;
    const int idx8 = lane & 7;

    const int qt = (int)gridDim.x - 1 - (int)blockIdx.x;
    const int h  = blockIdx.y;
    const int b  = blockIdx.z;
    const int bh = b * NHEADS + h;
    const __half* Qb = g_Qh + (size_t)bh * SEQ * HDIM;
    const __half* Kb = g_Kh + (size_t)bh * SEQ * HDIM;
    const __half* Vb = g_Vh + (size_t)bh * SEQ * HDIM;
    const int q0  = qt * QTILE;
    const int wr0 = q0 + wid * 16;

    uint32_t qa[4][4];
#pragma unroll
    for (int kb = 0; kb < 4; kb++) {
        const int col = kb * 16 + 2 * tq;
        qa[kb][0] = *(const uint32_t*)&Qb[(size_t)(wr0 + g) * HDIM + col];
        qa[kb][1] = *(const uint32_t*)&Qb[(size_t)(wr0 + g + 8) * HDIM + col];
        qa[kb][2] = *(const uint32_t*)&Qb[(size_t)(wr0 + g) * HDIM + col + 8];
        qa[kb][3] = *(const uint32_t*)&Qb[(size_t)(wr0 + g + 8) * HDIM + col + 8];
    }

    float m0 = -1e30f, m1 = -1e30f, l0 = 0.0f, l1 = 0.0f;
    float o[8][4];
#pragma unroll
    for (int nf = 0; nf < 8; nf++)
#pragma unroll
        for (int r = 0; r < 4; r++) o[nf][r] = 0.0f;

    const uint32_t ks_base = (uint32_t)__cvta_generic_to_shared(Ks);
    const uint32_t vs_base = (uint32_t)__cvta_generic_to_shared(Vs);

    const int lr = t >> 2;
    const int lc = (t & 3) * 4;

    auto load_kv = [&](int buf, int jt) {
        const __half* Kt = Kb + (size_t)jt * 64 * HDIM;
        const __half* Vt = Vb + (size_t)jt * 64 * HDIM;
        const uint32_t kd = ks_base + buf * KVB;
        const uint32_t vd = vs_base + buf * KVB;
        cp16(kd + (lr * KP + lc) * 4,        Kt + lr * HDIM + lc * 2);
        cp16(kd + (lr * KP + lc + 16) * 4,   Kt + lr * HDIM + (lc + 16) * 2);
        cp16(vd + (lr * KP + lc) * 4,        Vt + lr * HDIM + lc * 2);
        cp16(vd + (lr * KP + lc + 16) * 4,   Vt + lr * HDIM + (lc + 16) * 2);
        CP_COMMIT();
    };

    const int njt = (q0 + QTILE) / 64;
    load_kv(0, 0);

    for (int jt = 0; jt < njt; jt++) {
        if (jt + 1 < njt) { load_kv((jt + 1) & 1, jt + 1); cp_wait<1>(); }
        else              { cp_wait<0>(); }
        __syncthreads();

        const uint32_t kbase = ks_base + (jt & 1) * KVB;
        const uint32_t vbase = vs_base + (jt & 1) * KVB;

        if (jt * 64 <= wr0 + 15) {
            // ---- S = Q @ K^T ----
            float c[8][4];
#pragma unroll
            for (int nf = 0; nf < 8; nf++)
#pragma unroll
                for (int r = 0; r < 4; r++) c[nf][r] = 0.0f;

#pragma unroll
            for (int kb = 0; kb < 4; kb++) {
#pragma unroll
                for (int np = 0; np < 4; np++) {
                    const int krow = np * 16 + (quad >> 1) * 8 + idx8;
                    const int kwrd = kb * 8 + (quad & 1) * 4;
                    uint32_t r0, r1, r2, r3;
                    ldmatrix_x4(r0, r1, r2, r3, kbase + (uint32_t)((krow * KP + kwrd) * 4));
                    mma_f16(c[2 * np],     qa[kb][0], qa[kb][1], qa[kb][2], qa[kb][3], r0, r1);
                    mma_f16(c[2 * np + 1], qa[kb][0], qa[kb][1], qa[kb][2], qa[kb][3], r2, r3);
                }
            }

            // ---- scale + causal mask ----
            const bool diag = (jt * 64 + 63 > wr0);
#pragma unroll
            for (int nf = 0; nf < 8; nf++) {
#pragma unroll
                for (int r = 0; r < 4; r++) {
                    float v = c[nf][r] * 0.125f;
                    if (diag) {
                        const int col = jt * 64 + nf * 8 + 2 * tq + (r & 1);
                        const int row = wr0 + g + ((r >= 2) ? 8 : 0);
                        if (col > row) v = -1e30f;
                    }
                    c[nf][r] = v;
                }
            }

            // ---- online softmax ----
            float tm0 = -1e30f, tm1 = -1e30f;
#pragma unroll
            for (int nf = 0; nf < 8; nf++) {
                tm0 = fmaxf(tm0, fmaxf(c[nf][0], c[nf][1]));
                tm1 = fmaxf(tm1, fmaxf(c[nf][2], c[nf][3]));
            }
#pragma unroll
            for (int off = 1; off <= 2; off <<= 1) {
                tm0 = fmaxf(tm0, __shfl_xor_sync(0xffffffffu, tm0, off));
                tm1 = fmaxf(tm1, __shfl_xor_sync(0xffffffffu, tm1, off));
            }
            const float nm0 = fmaxf(m0, tm0);
            const float nm1 = fmaxf(m1, tm1);
            const float al0 = __expf(m0 - nm0);
            const float al1 = __expf(m1 - nm1);
            float rs0 = 0.0f, rs1 = 0.0f;
#pragma unroll
            for (int nf = 0; nf < 8; nf++) {
                c[nf][0] = __expf(c[nf][0] - nm0);
                c[nf][1] = __expf(c[nf][1] - nm0);
                c[nf][2] = __expf(c[nf][2] - nm1);
                c[nf][3] = __expf(c[nf][3] - nm1);
                rs0 += c[nf][0] + c[nf][1];
                rs1 += c[nf][2] + c[nf][3];
            }
#pragma unroll
            for (int off = 1; off <= 2; off <<= 1) {
                rs0 += __shfl_xor_sync(0xffffffffu, rs0, off);
                rs1 += __shfl_xor_sync(0xffffffffu, rs1, off);
            }
            l0 = l0 * al0 + rs0;  m0 = nm0;
            l1 = l1 * al1 + rs1;  m1 = nm1;
#pragma unroll
            for (int nf = 0; nf < 8; nf++) {
                o[nf][0] *= al0;  o[nf][1] *= al0;
                o[nf][2] *= al1;  o[nf][3] *= al1;
            }

            // ---- O += P @ V ----
#pragma unroll
            for (int kb2 = 0; kb2 < 4; kb2++) {
                const uint32_t a0 = pack_f16(c[2 * kb2][0],     c[2 * kb2][1]);
                const uint32_t a1 = pack_f16(c[2 * kb2][2],     c[2 * kb2][3]);
                const uint32_t a2 = pack_f16(c[2 * kb2 + 1][0], c[2 * kb2 + 1][1]);
                const uint32_t a3 = pack_f16(c[2 * kb2 + 1][2], c[2 * kb2 + 1][3]);
#pragma unroll
                for (int np = 0; np < 4; np++) {
                    const int vrow = kb2 * 16 + (quad & 1) * 8 + idx8;
                    const int vwrd = np * 8 + (quad >> 1) * 4;
                    uint32_t r0, r1, r2, r3;
                    ldmatrix_x4_trans(r0, r1, r2, r3,
                                      vbase + (uint32_t)((vrow * KP + vwrd) * 4));
                    mma_f16(o[2 * np],     a0, a1, a2, a3, r0, r1);
                    mma_f16(o[2 * np + 1], a0, a1, a2, a3, r2, r3);
                }
            }
        }
        __syncthreads();   // all reads of buffer jt&1 done before its next refill
    }

    // ---- normalize & store ctx as hi/lo bf16 ----
    const float inv0 = 1.0f / l0;
    const float inv1 = 1.0f / l1;
    const size_t r0off = ((size_t)(b * SEQ) + wr0 + g) * D_MODEL + h * HDIM;
    const size_t r1off = ((size_t)(b * SEQ) + wr0 + g + 8) * D_MODEL + h * HDIM;
#pragma unroll
    for (int nf = 0; nf < 8; nf++) {
        const int col = nf * 8 + 2 * tq;
        const float v0 = o[nf][0] * inv0, v1 = o[nf][1] * inv0;
        const float v2 = o[nf][2] * inv1, v3 = o[nf][3] * inv1;
        __nv_bfloat16 h0 = __float2bfloat16(v0), h1 = __float2bfloat16(v1);
        __nv_bfloat16 h2 = __float2bfloat16(v2), h3 = __float2bfloat16(v3);
        __nv_bfloat162 hp0; hp0.x = h0; hp0.y = h1;
        __nv_bfloat162 hp1; hp1.x = h2; hp1.y = h3;
        __nv_bfloat162 lp0;
        lp0.x = __float2bfloat16(v0 - __bfloat162float(h0));
        lp0.y = __float2bfloat16(v1 - __bfloat162float(h1));
        __nv_bfloat162 lp1;
        lp1.x = __float2bfloat16(v2 - __bfloat162float(h2));
        lp1.y = __float2bfloat16(v3 - __bfloat162float(h3));
        *(__nv_bfloat162*)&g_Ah[r0off + col] = hp0;
        *(__nv_bfloat162*)&g_Al[r0off + col] = lp0;
        *(__nv_bfloat162*)&g_Ah[r1off + col] = hp1;
        *(__nv_bfloat162*)&g_Al[r1off + col] = lp1;
    }
}

// =================================================================================
// Launch
// =================================================================================
extern "C" void kernel_launch(void* const* d_in, const int* in_sizes, int n_in,
                              void* d_out, int out_size)
{
    const float* x  = (const float*)d_in[0];
    const float* Wq = (const float*)d_in[1];
    const float* Wk = (const float*)d_in[2];
    const float* Wv = (const float*)d_in[3];
    const float* Wo = (const float*)d_in[4];
    float* out = (float*)d_out;

    cudaFuncSetAttribute(bf16_gemm2<1>, cudaFuncAttributeMaxDynamicSharedMemorySize, G2SMEM);
    cudaFuncSetAttribute(bf16_gemm2<0>, cudaFuncAttributeMaxDynamicSharedMemorySize, G2SMEM);

    split_x_kernel<<<NROWS * D_MODEL / 1024, 256>>>(x);
    split_w_kernel<<<dim3(D_MODEL * D_MODEL / 1024, 1, 4), 256>>>(Wq, Wk, Wv, Wo);

    bf16_gemm2<1><<<dim3(D_MODEL / 128, NROWS / 128, 3), 256, G2SMEM>>>(nullptr);

    attn_mma_kernel<<<dim3(SEQ / QTILE, NHEADS, BATCH), 256>>>();

    bf16_gemm2<0><<<dim3(D_MODEL / 128, NROWS / 128, 1), 256, G2SMEM>>>(out);
}

// round 12
// speedup vs baseline: 1.0176x; 1.0176x over previous
#include <cuda_runtime.h>
#include <cuda_bf16.h>
#include <cuda_fp16.h>
#include <cstdint>

#define D_MODEL 1024
#define NHEADS  16
#define HDIM    64
#define BATCH   2
#define SEQ     2048
#define NROWS   (BATCH * SEQ)   // 4096
#define QTILE   128

// ---------------- scratch (static device globals; no allocations) ----------------
__device__ __half g_Qh[BATCH * NHEADS * SEQ * HDIM];   // [B,H,S,Dh] fp16
__device__ __half g_Kh[BATCH * NHEADS * SEQ * HDIM];
__device__ __half g_Vh[BATCH * NHEADS * SEQ * HDIM];
__device__ __nv_bfloat16 g_Ah[NROWS * D_MODEL];        // A hi: x-split, then ctx-split
__device__ __nv_bfloat16 g_Al[NROWS * D_MODEL];        // A lo
__device__ __nv_bfloat16 g_Wh[4 * D_MODEL * D_MODEL];  // W hi [z][k][n]
__device__ __nv_bfloat16 g_Wl[4 * D_MODEL * D_MODEL];  // W lo

// ---------------- ptx helpers (sm_80-class only; NO tcgen05 on this target) ------
__device__ __forceinline__ void cp16(uint32_t smem, const void* gmem) {
    asm volatile("cp.async.cg.shared.global [%0], [%1], 16;" :: "r"(smem), "l"(gmem));
}
#define CP_COMMIT() asm volatile("cp.async.commit_group;" ::: "memory")
template <int N>
__device__ __forceinline__ void cp_wait() {
    asm volatile("cp.async.wait_group %0;" :: "n"(N) : "memory");
}

__device__ __forceinline__ void ldmatrix_x4(uint32_t& r0, uint32_t& r1,
                                            uint32_t& r2, uint32_t& r3, uint32_t addr) {
    asm volatile("ldmatrix.sync.aligned.m8n8.x4.shared.b16 {%0,%1,%2,%3}, [%4];"
                 : "=r"(r0), "=r"(r1), "=r"(r2), "=r"(r3) : "r"(addr));
}
__device__ __forceinline__ void ldmatrix_x4_trans(uint32_t& r0, uint32_t& r1,
                                                  uint32_t& r2, uint32_t& r3, uint32_t addr) {
    asm volatile("ldmatrix.sync.aligned.m8n8.x4.trans.shared.b16 {%0,%1,%2,%3}, [%4];"
                 : "=r"(r0), "=r"(r1), "=r"(r2), "=r"(r3) : "r"(addr));
}
__device__ __forceinline__ void mma_bf16(float* c,
    uint32_t a0, uint32_t a1, uint32_t a2, uint32_t a3, uint32_t b0, uint32_t b1)
{
    asm volatile(
        "mma.sync.aligned.m16n8k16.row.col.f32.bf16.bf16.f32 "
        "{%0,%1,%2,%3}, {%4,%5,%6,%7}, {%8,%9}, {%0,%1,%2,%3};\n"
        : "+f"(c[0]), "+f"(c[1]), "+f"(c[2]), "+f"(c[3])
        : "r"(a0), "r"(a1), "r"(a2), "r"(a3), "r"(b0), "r"(b1));
}
__device__ __forceinline__ void mma_f16(float* c,
    uint32_t a0, uint32_t a1, uint32_t a2, uint32_t a3, uint32_t b0, uint32_t b1)
{
    asm volatile(
        "mma.sync.aligned.m16n8k16.row.col.f32.f16.f16.f32 "
        "{%0,%1,%2,%3}, {%4,%5,%6,%7}, {%8,%9}, {%0,%1,%2,%3};\n"
        : "+f"(c[0]), "+f"(c[1]), "+f"(c[2]), "+f"(c[3])
        : "r"(a0), "r"(a1), "r"(a2), "r"(a3), "r"(b0), "r"(b1));
}
__device__ __forceinline__ uint32_t pack_f16(float x0, float x1) {
    __half2 h = __floats2half2_rn(x0, x1);
    return *(uint32_t*)&h;
}

// =================================================================================
// Pre-pass: element-wise hi/lo bf16 splits (no transpose; layouts preserved).
// =================================================================================
__global__ __launch_bounds__(256) void split_x_kernel(const float* __restrict__ src)
{
    const size_t i = ((size_t)blockIdx.x * 256 + threadIdx.x) * 4;
    float4 v = *(const float4*)(src + i);
    __nv_bfloat16 h[4] = {__float2bfloat16(v.x), __float2bfloat16(v.y),
                          __float2bfloat16(v.z), __float2bfloat16(v.w)};
    __nv_bfloat16 l[4] = {__float2bfloat16(v.x - __bfloat162float(h[0])),
                          __float2bfloat16(v.y - __bfloat162float(h[1])),
                          __float2bfloat16(v.z - __bfloat162float(h[2])),
                          __float2bfloat16(v.w - __bfloat162float(h[3]))};
    *(uint2*)(g_Ah + i) = *(uint2*)h;
    *(uint2*)(g_Al + i) = *(uint2*)l;
}
__global__ __launch_bounds__(256) void split_w_kernel(
    const float* __restrict__ W0, const float* __restrict__ W1,
    const float* __restrict__ W2, const float* __restrict__ W3)
{
    const float* W = (blockIdx.z == 0) ? W0 : (blockIdx.z == 1) ? W1
                   : (blockIdx.z == 2) ? W2 : W3;
    const size_t o = (size_t)blockIdx.z * D_MODEL * D_MODEL;
    const size_t i = ((size_t)blockIdx.x * 256 + threadIdx.x) * 4;
    float4 v = *(const float4*)(W + i);
    __nv_bfloat16 h[4] = {__float2bfloat16(v.x), __float2bfloat16(v.y),
                          __float2bfloat16(v.z), __float2bfloat16(v.w)};
    __nv_bfloat16 l[4] = {__float2bfloat16(v.x - __bfloat162float(h[0])),
                          __float2bfloat16(v.y - __bfloat162float(h[1])),
                          __float2bfloat16(v.z - __bfloat162float(h[2])),
                          __float2bfloat16(v.w - __bfloat162float(h[3]))};
    *(uint2*)(g_Wh + o + i) = *(uint2*)h;
    *(uint2*)(g_Wl + o + i) = *(uint2*)l;
}

// =================================================================================
// bf16-split 3-pass GEMM v2 (verified Round-10): cp.async double-buffered, BK=32.
// =================================================================================
#define STG_AH 0
#define STG_AL 10240
#define STG_BH 20480
#define STG_BL 29184
#define STG_SZ 37888
#define G2SMEM (2 * STG_SZ)   // 75776

template <int QKV>
__global__ __launch_bounds__(256) void bf16_gemm2(float* __restrict__ Cout)
{
    extern __shared__ uint8_t smem[];
    const uint32_t sb = (uint32_t)__cvta_generic_to_shared(smem);
    const int t = threadIdx.x, lane = t & 31, wid = t >> 5;
    const int g = lane >> 2, tq = lane & 3, quad = lane >> 3, idx8 = lane & 7;
    const int wm = (wid & 1) * 64, wn = (wid >> 1) * 32;
    const int m0 = blockIdx.y * 128, n0 = blockIdx.x * 128;
    const int z  = QKV ? (int)blockIdx.z : 3;

    const __nv_bfloat16* Wh = g_Wh + (size_t)z * D_MODEL * D_MODEL;
    const __nv_bfloat16* Wl = g_Wl + (size_t)z * D_MODEL * D_MODEL;

    const int arow0 = t >> 2;
    const int ak8   = (t & 3) * 8;
    const int brow0 = t >> 4;
    const int bn8   = (t & 15) * 8;

    float acc[4][4][4];
#pragma unroll
    for (int mf = 0; mf < 4; mf++)
#pragma unroll
        for (int nf = 0; nf < 4; nf++)
#pragma unroll
            for (int r = 0; r < 4; r++) acc[mf][nf][r] = 0.0f;

    auto load_stage = [&](int buf, int ks) {
        const uint32_t base = sb + buf * STG_SZ;
#pragma unroll
        for (int half = 0; half < 2; half++) {
            const int row = arow0 + half * 64;
            const uint32_t d = base + row * 80 + (t & 3) * 16;
            const size_t   s = (size_t)(m0 + row) * D_MODEL + ks + ak8;
            cp16(d + STG_AH, g_Ah + s);
            cp16(d + STG_AL, g_Al + s);
        }
#pragma unroll
        for (int half = 0; half < 2; half++) {
            const int row = brow0 + half * 16;
            const uint32_t d = base + row * 272 + (t & 15) * 16;
            const size_t   s = (size_t)(ks + row) * D_MODEL + n0 + bn8;
            cp16(d + STG_BH, Wh + s);
            cp16(d + STG_BL, Wl + s);
        }
        CP_COMMIT();
    };

    load_stage(0, 0);
    load_stage(1, 32);
    int ks = 64;

    constexpr int NIT = D_MODEL / 32;   // 32
    for (int it = 0; it < NIT; ++it) {
        if (it + 1 < NIT) cp_wait<1>(); else cp_wait<0>();
        __syncthreads();

        const uint32_t ab  = sb + (it & 1) * STG_SZ;
        const uint32_t aAh = ab + STG_AH, aAl = ab + STG_AL;
        const uint32_t aBh = ab + STG_BH, aBl = ab + STG_BL;

#pragma unroll
        for (int kb = 0; kb < 2; kb++) {
            uint32_t ah[4][4], al[4][4], bh[4][2], bl[4][2];
#pragma unroll
            for (int mf = 0; mf < 4; mf++) {
                const uint32_t off =
                    (uint32_t)((wm + mf * 16 + (lane & 15)) * 80 +
                               (kb * 8 + (lane >> 4) * 4) * 4);
                ldmatrix_x4(ah[mf][0], ah[mf][1], ah[mf][2], ah[mf][3], aAh + off);
                ldmatrix_x4(al[mf][0], al[mf][1], al[mf][2], al[mf][3], aAl + off);
            }
#pragma unroll
            for (int np = 0; np < 2; np++) {
                const uint32_t boff =
                    (uint32_t)((kb * 16 + (quad & 1) * 8 + idx8) * 272 +
                               (wn / 2 + np * 8 + (quad >> 1) * 4) * 4);
                uint32_t r0, r1, r2, r3;
                ldmatrix_x4_trans(r0, r1, r2, r3, aBh + boff);
                bh[2 * np][0] = r0; bh[2 * np][1] = r1;
                bh[2 * np + 1][0] = r2; bh[2 * np + 1][1] = r3;
                ldmatrix_x4_trans(r0, r1, r2, r3, aBl + boff);
                bl[2 * np][0] = r0; bl[2 * np][1] = r1;
                bl[2 * np + 1][0] = r2; bl[2 * np + 1][1] = r3;
            }
#pragma unroll
            for (int mf = 0; mf < 4; mf++)
#pragma unroll
                for (int nf = 0; nf < 4; nf++)
                    mma_bf16(acc[mf][nf], ah[mf][0], ah[mf][1], ah[mf][2], ah[mf][3],
                             bh[nf][0], bh[nf][1]);
#pragma unroll
            for (int mf = 0; mf < 4; mf++)
#pragma unroll
                for (int nf = 0; nf < 4; nf++)
                    mma_bf16(acc[mf][nf], al[mf][0], al[mf][1], al[mf][2], al[mf][3],
                             bh[nf][0], bh[nf][1]);
#pragma unroll
            for (int mf = 0; mf < 4; mf++)
#pragma unroll
                for (int nf = 0; nf < 4; nf++)
                    mma_bf16(acc[mf][nf], ah[mf][0], ah[mf][1], ah[mf][2], ah[mf][3],
                             bl[nf][0], bl[nf][1]);
        }
        __syncthreads();
        if (it + 2 < NIT) {
            load_stage(it & 1, ks);
            ks += 32;
        }
    }

#pragma unroll
    for (int mf = 0; mf < 4; mf++) {
#pragma unroll
        for (int nf = 0; nf < 4; nf++) {
            const int n = n0 + wn + nf * 8 + 2 * tq;
#pragma unroll
            for (int half = 0; half < 2; half++) {
                const int m = m0 + wm + mf * 16 + g + half * 8;
                const float c0 = acc[mf][nf][half * 2 + 0];
                const float c1 = acc[mf][nf][half * 2 + 1];
                if (QKV) {
                    const int b  = m >> 11;
                    const int s  = m & (SEQ - 1);
                    const int h  = n >> 6;
                    const int dd = n & (HDIM - 1);
                    __half2 hv = __floats2half2_rn(c0, c1);
                    __half* dst = (z == 0) ? g_Qh : (z == 1) ? g_Kh : g_Vh;
                    *(__half2*)&dst[(((size_t)(b * NHEADS + h)) * SEQ + s) * HDIM + dd] = hv;
                } else {
                    *(float2*)&Cout[(size_t)m * D_MODEL + n] = make_float2(c0, c1);
                }
            }
        }
    }
}

// =================================================================================
// fp16 tensor-core causal flash attention (verified Round-10 body) at 2 CTAs/SM.
// Block = 128 queries of one (b,h); 8 warps, warp-local softmax. Single-buffer
// KV tiles (18.4 KB smem) — Round-11 showed loads are NOT the binder; occupancy is.
// =================================================================================
__global__ __launch_bounds__(256, 2) void attn_mma_kernel()
{
    constexpr int KP = 36;
    __shared__ __align__(16) uint32_t Ks[64 * KP];
    __shared__ __align__(16) uint32_t Vs[64 * KP];

    const int t    = threadIdx.x;
    const int lane = t & 31;
    const int wid  = t >> 5;
    const int g    = lane >> 2;
    const int tq   = lane & 3;
    const int quad = lane >> 3;
    const int idx8 = lane & 7;

    const int qt = (int)gridDim.x - 1 - (int)blockIdx.x;
    const int h  = blockIdx.y;
    const int b  = blockIdx.z;
    const int bh = b * NHEADS + h;
    const __half* Qb = g_Qh + (size_t)bh * SEQ * HDIM;
    const __half* Kb = g_Kh + (size_t)bh * SEQ * HDIM;
    const __half* Vb = g_Vh + (size_t)bh * SEQ * HDIM;
    const int q0  = qt * QTILE;
    const int wr0 = q0 + wid * 16;

    uint32_t qa[4][4];
#pragma unroll
    for (int kb = 0; kb < 4; kb++) {
        const int col = kb * 16 + 2 * tq;
        qa[kb][0] = *(const uint32_t*)&Qb[(size_t)(wr0 + g) * HDIM + col];
        qa[kb][1] = *(const uint32_t*)&Qb[(size_t)(wr0 + g + 8) * HDIM + col];
        qa[kb][2] = *(const uint32_t*)&Qb[(size_t)(wr0 + g) * HDIM + col + 8];
        qa[kb][3] = *(const uint32_t*)&Qb[(size_t)(wr0 + g + 8) * HDIM + col + 8];
    }

    float m0 = -1e30f, m1 = -1e30f, l0 = 0.0f, l1 = 0.0f;
    float o[8][4];
#pragma unroll
    for (int nf = 0; nf < 8; nf++)
#pragma unroll
        for (int r = 0; r < 4; r++) o[nf][r] = 0.0f;

    const uint32_t ks_base = (uint32_t)__cvta_generic_to_shared(Ks);
    const uint32_t vs_base = (uint32_t)__cvta_generic_to_shared(Vs);

    const int lr = t >> 2;
    const int lc = (t & 3) * 4;

    const int njt = (q0 + QTILE) / 64;
    for (int jt = 0; jt < njt; jt++) {
        __syncthreads();
        const __half* Kt = Kb + (size_t)jt * 64 * HDIM;
        const __half* Vt = Vb + (size_t)jt * 64 * HDIM;
        *(uint4*)&Ks[lr * KP + lc]      = *(const uint4*)&Kt[lr * HDIM + lc * 2];
        *(uint4*)&Ks[lr * KP + lc + 16] = *(const uint4*)&Kt[lr * HDIM + (lc + 16) * 2];
        *(uint4*)&Vs[lr * KP + lc]      = *(const uint4*)&Vt[lr * HDIM + lc * 2];
        *(uint4*)&Vs[lr * KP + lc + 16] = *(const uint4*)&Vt[lr * HDIM + (lc + 16) * 2];
        __syncthreads();

        if (jt * 64 > wr0 + 15) continue;

        float c[8][4];
#pragma unroll
        for (int nf = 0; nf < 8; nf++)
#pragma unroll
            for (int r = 0; r < 4; r++) c[nf][r] = 0.0f;

#pragma unroll
        for (int kb = 0; kb < 4; kb++) {
#pragma unroll
            for (int np = 0; np < 4; np++) {
                const int krow = np * 16 + (quad >> 1) * 8 + idx8;
                const int kwrd = kb * 8 + (quad & 1) * 4;
                uint32_t r0, r1, r2, r3;
                ldmatrix_x4(r0, r1, r2, r3, ks_base + (uint32_t)((krow * KP + kwrd) * 4));
                mma_f16(c[2 * np],     qa[kb][0], qa[kb][1], qa[kb][2], qa[kb][3], r0, r1);
                mma_f16(c[2 * np + 1], qa[kb][0], qa[kb][1], qa[kb][2], qa[kb][3], r2, r3);
            }
        }

        const bool diag = (jt * 64 + 63 > wr0);
#pragma unroll
        for (int nf = 0; nf < 8; nf++) {
#pragma unroll
            for (int r = 0; r < 4; r++) {
                float v = c[nf][r] * 0.125f;
                if (diag) {
                    const int col = jt * 64 + nf * 8 + 2 * tq + (r & 1);
                    const int row = wr0 + g + ((r >= 2) ? 8 : 0);
                    if (col > row) v = -1e30f;
                }
                c[nf][r] = v;
            }
        }

        float tm0 = -1e30f, tm1 = -1e30f;
#pragma unroll
        for (int nf = 0; nf < 8; nf++) {
            tm0 = fmaxf(tm0, fmaxf(c[nf][0], c[nf][1]));
            tm1 = fmaxf(tm1, fmaxf(c[nf][2], c[nf][3]));
        }
#pragma unroll
        for (int off = 1; off <= 2; off <<= 1) {
            tm0 = fmaxf(tm0, __shfl_xor_sync(0xffffffffu, tm0, off));
            tm1 = fmaxf(tm1, __shfl_xor_sync(0xffffffffu, tm1, off));
        }
        const float nm0 = fmaxf(m0, tm0);
        const float nm1 = fmaxf(m1, tm1);
        const float al0 = __expf(m0 - nm0);
        const float al1 = __expf(m1 - nm1);
        float rs0 = 0.0f, rs1 = 0.0f;
#pragma unroll
        for (int nf = 0; nf < 8; nf++) {
            c[nf][0] = __expf(c[nf][0] - nm0);
            c[nf][1] = __expf(c[nf][1] - nm0);
            c[nf][2] = __expf(c[nf][2] - nm1);
            c[nf][3] = __expf(c[nf][3] - nm1);
            rs0 += c[nf][0] + c[nf][1];
            rs1 += c[nf][2] + c[nf][3];
        }
#pragma unroll
        for (int off = 1; off <= 2; off <<= 1) {
            rs0 += __shfl_xor_sync(0xffffffffu, rs0, off);
            rs1 += __shfl_xor_sync(0xffffffffu, rs1, off);
        }
        l0 = l0 * al0 + rs0;  m0 = nm0;
        l1 = l1 * al1 + rs1;  m1 = nm1;
#pragma unroll
        for (int nf = 0; nf < 8; nf++) {
            o[nf][0] *= al0;  o[nf][1] *= al0;
            o[nf][2] *= al1;  o[nf][3] *= al1;
        }

#pragma unroll
        for (int kb2 = 0; kb2 < 4; kb2++) {
            const uint32_t a0 = pack_f16(c[2 * kb2][0],     c[2 * kb2][1]);
            const uint32_t a1 = pack_f16(c[2 * kb2][2],     c[2 * kb2][3]);
            const uint32_t a2 = pack_f16(c[2 * kb2 + 1][0], c[2 * kb2 + 1][1]);
            const uint32_t a3 = pack_f16(c[2 * kb2 + 1][2], c[2 * kb2 + 1][3]);
#pragma unroll
            for (int np = 0; np < 4; np++) {
                const int vrow = kb2 * 16 + (quad & 1) * 8 + idx8;
                const int vwrd = np * 8 + (quad >> 1) * 4;
                uint32_t r0, r1, r2, r3;
                ldmatrix_x4_trans(r0, r1, r2, r3, vs_base + (uint32_t)((vrow * KP + vwrd) * 4));
                mma_f16(o[2 * np],     a0, a1, a2, a3, r0, r1);
                mma_f16(o[2 * np + 1], a0, a1, a2, a3, r2, r3);
            }
        }
    }

    // ---- normalize & store ctx as hi/lo bf16 ----
    const float inv0 = 1.0f / l0;
    const float inv1 = 1.0f / l1;
    const size_t r0off = ((size_t)(b * SEQ) + wr0 + g) * D_MODEL + h * HDIM;
    const size_t r1off = ((size_t)(b * SEQ) + wr0 + g + 8) * D_MODEL + h * HDIM;
#pragma unroll
    for (int nf = 0; nf < 8; nf++) {
        const int col = nf * 8 + 2 * tq;
        const float v0 = o[nf][0] * inv0, v1 = o[nf][1] * inv0;
        const float v2 = o[nf][2] * inv1, v3 = o[nf][3] * inv1;
        __nv_bfloat16 h0 = __float2bfloat16(v0), h1 = __float2bfloat16(v1);
        __nv_bfloat16 h2 = __float2bfloat16(v2), h3 = __float2bfloat16(v3);
        __nv_bfloat162 hp0; hp0.x = h0; hp0.y = h1;
        __nv_bfloat162 hp1; hp1.x = h2; hp1.y = h3;
        __nv_bfloat162 lp0;
        lp0.x = __float2bfloat16(v0 - __bfloat162float(h0));
        lp0.y = __float2bfloat16(v1 - __bfloat162float(h1));
        __nv_bfloat162 lp1;
        lp1.x = __float2bfloat16(v2 - __bfloat162float(h2));
        lp1.y = __float2bfloat16(v3 - __bfloat162float(h3));
        *(__nv_bfloat162*)&g_Ah[r0off + col] = hp0;
        *(__nv_bfloat162*)&g_Al[r0off + col] = lp0;
        *(__nv_bfloat162*)&g_Ah[r1off + col] = hp1;
        *(__nv_bfloat162*)&g_Al[r1off + col] = lp1;
    }
}

// =================================================================================
// Launch
// =================================================================================
extern "C" void kernel_launch(void* const* d_in, const int* in_sizes, int n_in,
                              void* d_out, int out_size)
{
    const float* x  = (const float*)d_in[0];
    const float* Wq = (const float*)d_in[1];
    const float* Wk = (const float*)d_in[2];
    const float* Wv = (const float*)d_in[3];
    const float* Wo = (const float*)d_in[4];
    float* out = (float*)d_out;

    cudaFuncSetAttribute(bf16_gemm2<1>, cudaFuncAttributeMaxDynamicSharedMemorySize, G2SMEM);
    cudaFuncSetAttribute(bf16_gemm2<0>, cudaFuncAttributeMaxDynamicSharedMemorySize, G2SMEM);

    split_x_kernel<<<NROWS * D_MODEL / 1024, 256>>>(x);
    split_w_kernel<<<dim3(D_MODEL * D_MODEL / 1024, 1, 4), 256>>>(Wq, Wk, Wv, Wo);

    bf16_gemm2<1><<<dim3(D_MODEL / 128, NROWS / 128, 3), 256, G2SMEM>>>(nullptr);

    attn_mma_kernel<<<dim3(SEQ / QTILE, NHEADS, BATCH), 256>>>();

    bf16_gemm2<0><<<dim3(D_MODEL / 128, NROWS / 128, 1), 256, G2SMEM>>>(out);
}

// round 13
// speedup vs baseline: 1.9801x; 1.9459x over previous
#include <cuda_runtime.h>
#include <cuda_fp16.h>
#include <cstdint>

#define D_MODEL 1024
#define NHEADS  16
#define HDIM    64
#define BATCH   2
#define SEQ     2048
#define NROWS   (BATCH * SEQ)   // 4096
#define QTILE   128

// 0.125 * log2(e): folded into Wq so attention scores are in log2 units pre-scaled
#define QSCALE 0.18033688011112042f

// ---------------- scratch (static device globals; no allocations) ----------------
__device__ __half g_Qh[BATCH * NHEADS * SEQ * HDIM];   // [B,H,S,Dh] fp16
__device__ __half g_Kh[BATCH * NHEADS * SEQ * HDIM];
__device__ __half g_Vh[BATCH * NHEADS * SEQ * HDIM];
__device__ __half g_Xh[NROWS * D_MODEL];               // fp16: x, then ctx
__device__ __half g_Wh[4 * D_MODEL * D_MODEL];         // fp16 W [z][k][n] (Wq pre-scaled)

// ---------------- ptx helpers (sm_80-class only; NO tcgen05 on this target) ------
__device__ __forceinline__ void cp16(uint32_t smem, const void* gmem) {
    asm volatile("cp.async.cg.shared.global [%0], [%1], 16;" :: "r"(smem), "l"(gmem));
}
#define CP_COMMIT() asm volatile("cp.async.commit_group;" ::: "memory")
template <int N>
__device__ __forceinline__ void cp_wait() {
    asm volatile("cp.async.wait_group %0;" :: "n"(N) : "memory");
}
__device__ __forceinline__ float ex2(float x) {
    float y;
    asm("ex2.approx.f32 %0, %1;" : "=f"(y) : "f"(x));
    return y;
}
__device__ __forceinline__ void ldmatrix_x4(uint32_t& r0, uint32_t& r1,
                                            uint32_t& r2, uint32_t& r3, uint32_t addr) {
    asm volatile("ldmatrix.sync.aligned.m8n8.x4.shared.b16 {%0,%1,%2,%3}, [%4];"
                 : "=r"(r0), "=r"(r1), "=r"(r2), "=r"(r3) : "r"(addr));
}
__device__ __forceinline__ void ldmatrix_x4_trans(uint32_t& r0, uint32_t& r1,
                                                  uint32_t& r2, uint32_t& r3, uint32_t addr) {
    asm volatile("ldmatrix.sync.aligned.m8n8.x4.trans.shared.b16 {%0,%1,%2,%3}, [%4];"
                 : "=r"(r0), "=r"(r1), "=r"(r2), "=r"(r3) : "r"(addr));
}
__device__ __forceinline__ void mma_f16(float* c,
    uint32_t a0, uint32_t a1, uint32_t a2, uint32_t a3, uint32_t b0, uint32_t b1)
{
    asm volatile(
        "mma.sync.aligned.m16n8k16.row.col.f32.f16.f16.f32 "
        "{%0,%1,%2,%3}, {%4,%5,%6,%7}, {%8,%9}, {%0,%1,%2,%3};\n"
        : "+f"(c[0]), "+f"(c[1]), "+f"(c[2]), "+f"(c[3])
        : "r"(a0), "r"(a1), "r"(a2), "r"(a3), "r"(b0), "r"(b1));
}
__device__ __forceinline__ uint32_t pack_f16(float x0, float x1) {
    __half2 h = __floats2half2_rn(x0, x1);
    return *(uint32_t*)&h;
}

// =================================================================================
// Pre-pass: fp16 conversions. Wq is pre-scaled by QSCALE (attention scale fold).
// =================================================================================
__global__ __launch_bounds__(256) void conv_x_kernel(const float* __restrict__ src)
{
    const size_t i = ((size_t)blockIdx.x * 256 + threadIdx.x) * 4;
    float4 v = *(const float4*)(src + i);
    __half2 p0 = __floats2half2_rn(v.x, v.y);
    __half2 p1 = __floats2half2_rn(v.z, v.w);
    *(uint2*)(g_Xh + i) = make_uint2(*(uint32_t*)&p0, *(uint32_t*)&p1);
}
__global__ __launch_bounds__(256) void conv_w_kernel(
    const float* __restrict__ W0, const float* __restrict__ W1,
    const float* __restrict__ W2, const float* __restrict__ W3)
{
    const float* W = (blockIdx.z == 0) ? W0 : (blockIdx.z == 1) ? W1
                   : (blockIdx.z == 2) ? W2 : W3;
    const float s = (blockIdx.z == 0) ? QSCALE : 1.0f;
    const size_t o = (size_t)blockIdx.z * D_MODEL * D_MODEL;
    const size_t i = ((size_t)blockIdx.x * 256 + threadIdx.x) * 4;
    float4 v = *(const float4*)(W + i);
    __half2 p0 = __floats2half2_rn(v.x * s, v.y * s);
    __half2 p1 = __floats2half2_rn(v.z * s, v.w * s);
    *(uint2*)(g_Wh + o + i) = make_uint2(*(uint32_t*)&p0, *(uint32_t*)&p1);
}

// =================================================================================
// fp16 1-pass GEMM: cp.async double-buffered, BK=32, block 128x128, 8 warps (2x4).
// A smem [m][k] pitch 80B (ldmatrix.x4); B smem [k][n] pitch 272B (ldmatrix.trans).
// QKV=1: A=g_Xh(x), B=g_Wh[z], out -> fp16 g_Qh/g_Kh/g_Vh [B,H,S,Dh].
// QKV=0: A=g_Xh(ctx), B=g_Wh[3](Wo), out -> fp32 row-major Cout.
// =================================================================================
#define STG_A 0
#define STG_B 10240
#define STG_SZ 18944
#define GSMEM (2 * STG_SZ)   // 37888 (fits default 48KB dynamic smem)

template <int QKV>
__global__ __launch_bounds__(256, 2) void f16_gemm(float* __restrict__ Cout)
{
    extern __shared__ uint8_t smem[];
    const uint32_t sb = (uint32_t)__cvta_generic_to_shared(smem);
    const int t = threadIdx.x, lane = t & 31, wid = t >> 5;
    const int g = lane >> 2, tq = lane & 3, quad = lane >> 3, idx8 = lane & 7;
    const int wm = (wid & 1) * 64, wn = (wid >> 1) * 32;
    const int m0 = blockIdx.y * 128, n0 = blockIdx.x * 128;
    const int z  = QKV ? (int)blockIdx.z : 3;

    const __half* A  = g_Xh;
    const __half* Wp = g_Wh + (size_t)z * D_MODEL * D_MODEL;

    float acc[4][4][4];
#pragma unroll
    for (int mf = 0; mf < 4; mf++)
#pragma unroll
        for (int nf = 0; nf < 4; nf++)
#pragma unroll
            for (int r = 0; r < 4; r++) acc[mf][nf][r] = 0.0f;

    auto load_stage = [&](int buf, int ks) {
        const uint32_t base = sb + buf * STG_SZ;
#pragma unroll
        for (int half = 0; half < 2; half++) {
            const int row = (t >> 2) + half * 64;
            cp16(base + STG_A + row * 80 + (t & 3) * 16,
                 A + (size_t)(m0 + row) * D_MODEL + ks + (t & 3) * 8);
        }
#pragma unroll
        for (int half = 0; half < 2; half++) {
            const int row = (t >> 4) + half * 16;
            cp16(base + STG_B + row * 272 + (t & 15) * 16,
                 Wp + (size_t)(ks + row) * D_MODEL + n0 + (t & 15) * 8);
        }
        CP_COMMIT();
    };

    load_stage(0, 0);
    load_stage(1, 32);
    int ks = 64;

    constexpr int NIT = D_MODEL / 32;   // 32
    for (int it = 0; it < NIT; ++it) {
        if (it + 1 < NIT) cp_wait<1>(); else cp_wait<0>();
        __syncthreads();

        const uint32_t ab = sb + (it & 1) * STG_SZ;
        const uint32_t aA = ab + STG_A, aB = ab + STG_B;

#pragma unroll
        for (int kb = 0; kb < 2; kb++) {
            uint32_t af[4][4], bf[4][2];
#pragma unroll
            for (int mf = 0; mf < 4; mf++) {
                const uint32_t off =
                    (uint32_t)((wm + mf * 16 + (lane & 15)) * 80 +
                               (kb * 8 + (lane >> 4) * 4) * 4);
                ldmatrix_x4(af[mf][0], af[mf][1], af[mf][2], af[mf][3], aA + off);
            }
#pragma unroll
            for (int np = 0; np < 2; np++) {
                const uint32_t boff =
                    (uint32_t)((kb * 16 + (quad & 1) * 8 + idx8) * 272 +
                               (wn / 2 + np * 8 + (quad >> 1) * 4) * 4);
                uint32_t r0, r1, r2, r3;
                ldmatrix_x4_trans(r0, r1, r2, r3, aB + boff);
                bf[2 * np][0] = r0; bf[2 * np][1] = r1;
                bf[2 * np + 1][0] = r2; bf[2 * np + 1][1] = r3;
            }
#pragma unroll
            for (int mf = 0; mf < 4; mf++)
#pragma unroll
                for (int nf = 0; nf < 4; nf++)
                    mma_f16(acc[mf][nf], af[mf][0], af[mf][1], af[mf][2], af[mf][3],
                            bf[nf][0], bf[nf][1]);
        }
        __syncthreads();
        if (it + 2 < NIT) {
            load_stage(it & 1, ks);
            ks += 32;
        }
    }

    // epilogue (verified layout): c0=(g,2tq) c1=(g,2tq+1) c2=(g+8,2tq) c3=(g+8,2tq+1)
#pragma unroll
    for (int mf = 0; mf < 4; mf++) {
#pragma unroll
        for (int nf = 0; nf < 4; nf++) {
            const int n = n0 + wn + nf * 8 + 2 * tq;
#pragma unroll
            for (int half = 0; half < 2; half++) {
                const int m = m0 + wm + mf * 16 + g + half * 8;
                const float c0 = acc[mf][nf][half * 2 + 0];
                const float c1 = acc[mf][nf][half * 2 + 1];
                if (QKV) {
                    const int b  = m >> 11;
                    const int s  = m & (SEQ - 1);
                    const int h  = n >> 6;
                    const int dd = n & (HDIM - 1);
                    __half2 hv = __floats2half2_rn(c0, c1);
                    __half* dst = (z == 0) ? g_Qh : (z == 1) ? g_Kh : g_Vh;
                    *(__half2*)&dst[(((size_t)(b * NHEADS + h)) * SEQ + s) * HDIM + dd] = hv;
                } else {
                    *(float2*)&Cout[(size_t)m * D_MODEL + n] = make_float2(c0, c1);
                }
            }
        }
    }
}

// =================================================================================
// fp16 tensor-core causal flash attention (verified Round-10/12 body).
// Q pre-scaled by 0.125*log2(e) (folded into Wq) -> scores in log2 units, exp=EX2.
// Epilogue writes ctx as fp16 into g_Xh (feeds the out-proj GEMM).
// =================================================================================
__global__ __launch_bounds__(256, 2) void attn_mma_kernel()
{
    constexpr int KP = 36;
    __shared__ __align__(16) uint32_t Ks[64 * KP];
    __shared__ __align__(16) uint32_t Vs[64 * KP];

    const int t    = threadIdx.x;
    const int lane = t & 31;
    const int wid  = t >> 5;
    const int g    = lane >> 2;
    const int tq   = lane & 3;
    const int quad = lane >> 3;
    const int idx8 = lane & 7;

    const int qt = (int)gridDim.x - 1 - (int)blockIdx.x;
    const int h  = blockIdx.y;
    const int b  = blockIdx.z;
    const int bh = b * NHEADS + h;
    const __half* Qb = g_Qh + (size_t)bh * SEQ * HDIM;
    const __half* Kb = g_Kh + (size_t)bh * SEQ * HDIM;
    const __half* Vb = g_Vh + (size_t)bh * SEQ * HDIM;
    const int q0  = qt * QTILE;
    const int wr0 = q0 + wid * 16;

    uint32_t qa[4][4];
#pragma unroll
    for (int kb = 0; kb < 4; kb++) {
        const int col = kb * 16 + 2 * tq;
        qa[kb][0] = *(const uint32_t*)&Qb[(size_t)(wr0 + g) * HDIM + col];
        qa[kb][1] = *(const uint32_t*)&Qb[(size_t)(wr0 + g + 8) * HDIM + col];
        qa[kb][2] = *(const uint32_t*)&Qb[(size_t)(wr0 + g) * HDIM + col + 8];
        qa[kb][3] = *(const uint32_t*)&Qb[(size_t)(wr0 + g + 8) * HDIM + col + 8];
    }

    float m0 = -1e30f, m1 = -1e30f, l0 = 0.0f, l1 = 0.0f;
    float o[8][4];
#pragma unroll
    for (int nf = 0; nf < 8; nf++)
#pragma unroll
        for (int r = 0; r < 4; r++) o[nf][r] = 0.0f;

    const uint32_t ks_base = (uint32_t)__cvta_generic_to_shared(Ks);
    const uint32_t vs_base = (uint32_t)__cvta_generic_to_shared(Vs);

    const int lr = t >> 2;
    const int lc = (t & 3) * 4;

    const int njt = (q0 + QTILE) / 64;
    for (int jt = 0; jt < njt; jt++) {
        __syncthreads();
        const __half* Kt = Kb + (size_t)jt * 64 * HDIM;
        const __half* Vt = Vb + (size_t)jt * 64 * HDIM;
        *(uint4*)&Ks[lr * KP + lc]      = *(const uint4*)&Kt[lr * HDIM + lc * 2];
        *(uint4*)&Ks[lr * KP + lc + 16] = *(const uint4*)&Kt[lr * HDIM + (lc + 16) * 2];
        *(uint4*)&Vs[lr * KP + lc]      = *(const uint4*)&Vt[lr * HDIM + lc * 2];
        *(uint4*)&Vs[lr * KP + lc + 16] = *(const uint4*)&Vt[lr * HDIM + (lc + 16) * 2];
        __syncthreads();

        if (jt * 64 > wr0 + 15) continue;

        float c[8][4];
#pragma unroll
        for (int nf = 0; nf < 8; nf++)
#pragma unroll
            for (int r = 0; r < 4; r++) c[nf][r] = 0.0f;

#pragma unroll
        for (int kb = 0; kb < 4; kb++) {
#pragma unroll
            for (int np = 0; np < 4; np++) {
                const int krow = np * 16 + (quad >> 1) * 8 + idx8;
                const int kwrd = kb * 8 + (quad & 1) * 4;
                uint32_t r0, r1, r2, r3;
                ldmatrix_x4(r0, r1, r2, r3, ks_base + (uint32_t)((krow * KP + kwrd) * 4));
                mma_f16(c[2 * np],     qa[kb][0], qa[kb][1], qa[kb][2], qa[kb][3], r0, r1);
                mma_f16(c[2 * np + 1], qa[kb][0], qa[kb][1], qa[kb][2], qa[kb][3], r2, r3);
            }
        }

        // causal mask (scores already scaled via Wq fold); only diagonal tiles mask
        const bool diag = (jt * 64 + 63 > wr0);
        if (diag) {
#pragma unroll
            for (int nf = 0; nf < 8; nf++) {
#pragma unroll
                for (int r = 0; r < 4; r++) {
                    const int col = jt * 64 + nf * 8 + 2 * tq + (r & 1);
                    const int row = wr0 + g + ((r >= 2) ? 8 : 0);
                    if (col > row) c[nf][r] = -1e30f;
                }
            }
        }

        // online softmax in log2 domain (EX2)
        float tm0 = -1e30f, tm1 = -1e30f;
#pragma unroll
        for (int nf = 0; nf < 8; nf++) {
            tm0 = fmaxf(tm0, fmaxf(c[nf][0], c[nf][1]));
            tm1 = fmaxf(tm1, fmaxf(c[nf][2], c[nf][3]));
        }
#pragma unroll
        for (int off = 1; off <= 2; off <<= 1) {
            tm0 = fmaxf(tm0, __shfl_xor_sync(0xffffffffu, tm0, off));
            tm1 = fmaxf(tm1, __shfl_xor_sync(0xffffffffu, tm1, off));
        }
        const float nm0 = fmaxf(m0, tm0);
        const float nm1 = fmaxf(m1, tm1);
        const float al0 = ex2(m0 - nm0);
        const float al1 = ex2(m1 - nm1);
        float rs0 = 0.0f, rs1 = 0.0f;
#pragma unroll
        for (int nf = 0; nf < 8; nf++) {
            c[nf][0] = ex2(c[nf][0] - nm0);
            c[nf][1] = ex2(c[nf][1] - nm0);
            c[nf][2] = ex2(c[nf][2] - nm1);
            c[nf][3] = ex2(c[nf][3] - nm1);
            rs0 += c[nf][0] + c[nf][1];
            rs1 += c[nf][2] + c[nf][3];
        }
#pragma unroll
        for (int off = 1; off <= 2; off <<= 1) {
            rs0 += __shfl_xor_sync(0xffffffffu, rs0, off);
            rs1 += __shfl_xor_sync(0xffffffffu, rs1, off);
        }
        l0 = l0 * al0 + rs0;  m0 = nm0;
        l1 = l1 * al1 + rs1;  m1 = nm1;
#pragma unroll
        for (int nf = 0; nf < 8; nf++) {
            o[nf][0] *= al0;  o[nf][1] *= al0;
            o[nf][2] *= al1;  o[nf][3] *= al1;
        }

#pragma unroll
        for (int kb2 = 0; kb2 < 4; kb2++) {
            const uint32_t a0 = pack_f16(c[2 * kb2][0],     c[2 * kb2][1]);
            const uint32_t a1 = pack_f16(c[2 * kb2][2],     c[2 * kb2][3]);
            const uint32_t a2 = pack_f16(c[2 * kb2 + 1][0], c[2 * kb2 + 1][1]);
            const uint32_t a3 = pack_f16(c[2 * kb2 + 1][2], c[2 * kb2 + 1][3]);
#pragma unroll
            for (int np = 0; np < 4; np++) {
                const int vrow = kb2 * 16 + (quad & 1) * 8 + idx8;
                const int vwrd = np * 8 + (quad >> 1) * 4;
                uint32_t r0, r1, r2, r3;
                ldmatrix_x4_trans(r0, r1, r2, r3, vs_base + (uint32_t)((vrow * KP + vwrd) * 4));
                mma_f16(o[2 * np],     a0, a1, a2, a3, r0, r1);
                mma_f16(o[2 * np + 1], a0, a1, a2, a3, r2, r3);
            }
        }
    }

    // ---- normalize & store ctx as fp16 into g_Xh ----
    const float inv0 = 1.0f / l0;
    const float inv1 = 1.0f / l1;
    const size_t r0off = ((size_t)(b * SEQ) + wr0 + g) * D_MODEL + h * HDIM;
    const size_t r1off = ((size_t)(b * SEQ) + wr0 + g + 8) * D_MODEL + h * HDIM;
#pragma unroll
    for (int nf = 0; nf < 8; nf++) {
        const int col = nf * 8 + 2 * tq;
        __half2 p0 = __floats2half2_rn(o[nf][0] * inv0, o[nf][1] * inv0);
        __half2 p1 = __floats2half2_rn(o[nf][2] * inv1, o[nf][3] * inv1);
        *(__half2*)&g_Xh[r0off + col] = p0;
        *(__half2*)&g_Xh[r1off + col] = p1;
    }
}

// =================================================================================
// Launch
// =================================================================================
extern "C" void kernel_launch(void* const* d_in, const int* in_sizes, int n_in,
                              void* d_out, int out_size)
{
    const float* x  = (const float*)d_in[0];
    const float* Wq = (const float*)d_in[1];
    const float* Wk = (const float*)d_in[2];
    const float* Wv = (const float*)d_in[3];
    const float* Wo = (const float*)d_in[4];
    float* out = (float*)d_out;

    conv_x_kernel<<<NROWS * D_MODEL / 1024, 256>>>(x);
    conv_w_kernel<<<dim3(D_MODEL * D_MODEL / 1024, 1, 4), 256>>>(Wq, Wk, Wv, Wo);

    f16_gemm<1><<<dim3(D_MODEL / 128, NROWS / 128, 3), 256, GSMEM>>>(nullptr);

    attn_mma_kernel<<<dim3(SEQ / QTILE, NHEADS, BATCH), 256>>>();

    f16_gemm<0><<<dim3(D_MODEL / 128, NROWS / 128, 1), 256, GSMEM>>>(out);
}